// round 1
// baseline (speedup 1.0000x reference)
#include <cuda_runtime.h>
#include <cstdint>

// ---------------------------------------------------------------------------
// LoRARowParallelLinear: y = x @ W^T + bias + scatter-add LoRA (SGMV)
//   T=8192, D_IN=4096, D_OUT=4096, S=8, R=16, all fp32.
// Strategy: tf32 mma.sync GEMM (round-to-nearest tf32 conversion for accuracy)
//   Pass A: u_all = (x @ lora_A_flat^T) * scaling   -> scratch [8192 x 128]
//   Pass B: y = x @ W^T + bias + u_all[t, slot*16:+16] . lora_B[slot, o, :]
// ---------------------------------------------------------------------------

namespace {
constexpr int TOK   = 8192;
constexpr int DIN   = 4096;
constexpr int DOUT  = 4096;
constexpr int RANK  = 16;

constexpr int BM = 128, BN = 128, BK = 16;
constexpr int PITCH   = 20;                 // smem row pitch in words (16 + 4 pad)
constexpr int STAGES  = 4;
constexpr int TILE_W  = BM * PITCH;         // 2560 words / tile / matrix
constexpr int STAGE_W = 2 * TILE_W;         // A + B
constexpr int SMEM_BYTES = STAGES * STAGE_W * 4;  // 81920 B
}

// scratch for scaled LoRA-A activations (allocation-free: __device__ global)
__device__ float g_u[TOK * 128];

static __device__ __forceinline__ uint32_t f2tf(float f) {
    uint32_t u;
    asm("cvt.rna.tf32.f32 %0, %1;" : "=r"(u) : "f"(f));
    return u;
}

static __device__ __forceinline__ void mma_tf32(
    float& d0, float& d1, float& d2, float& d3,
    uint32_t a0, uint32_t a1, uint32_t a2, uint32_t a3,
    uint32_t b0, uint32_t b1)
{
    asm volatile(
        "mma.sync.aligned.m16n8k8.row.col.f32.tf32.tf32.f32 "
        "{%0,%1,%2,%3},{%4,%5,%6,%7},{%8,%9},{%0,%1,%2,%3};"
        : "+f"(d0), "+f"(d1), "+f"(d2), "+f"(d3)
        : "r"(a0), "r"(a1), "r"(a2), "r"(a3), "r"(b0), "r"(b1));
}

static __device__ __forceinline__ void cp_async16(float* smem_dst, const float* gsrc) {
    uint32_t s = (uint32_t)__cvta_generic_to_shared(smem_dst);
    asm volatile("cp.async.cg.shared.global [%0], [%1], 16;" :: "r"(s), "l"(gsrc));
}
static __device__ __forceinline__ void cp_commit() {
    asm volatile("cp.async.commit_group;");
}
template <int N>
static __device__ __forceinline__ void cp_wait() {
    asm volatile("cp.async.wait_group %0;" :: "n"(N));
}

static __device__ __forceinline__ float dot16(const float4 u[4], const float* b) {
    const float4* bp = reinterpret_cast<const float4*>(b);
    float4 b0 = bp[0], b1 = bp[1], b2 = bp[2], b3 = bp[3];
    float s = 0.f;
    s += u[0].x * b0.x + u[0].y * b0.y + u[0].z * b0.z + u[0].w * b0.w;
    s += u[1].x * b1.x + u[1].y * b1.y + u[1].z * b1.z + u[1].w * b1.w;
    s += u[2].x * b2.x + u[2].y * b2.y + u[2].z * b2.z + u[2].w * b2.w;
    s += u[3].x * b3.x + u[3].y * b3.y + u[3].z * b3.z + u[3].w * b3.w;
    return s;
}

// MODE 0: u-pass (C = g_u, pitch 128, scaled by lora_scaling)
// MODE 1: main pass (C = y, pitch DOUT, + bias + LoRA-B epilogue)
template <int MODE>
__global__ void __launch_bounds__(256, 1) gemm_tf32(
    const float* __restrict__ A,      // [M][K] row-major (x)
    const float* __restrict__ B,      // [N][K] row-major (W or lora_A flat)
    float* __restrict__ C,
    const float* __restrict__ bias,
    const int* __restrict__ t2s,
    const float* __restrict__ loraB,  // [S][DOUT][RANK]
    const float* __restrict__ scal)   // [S]
{
    extern __shared__ float sm[];
    const int tid  = threadIdx.x;
    const int lane = tid & 31;
    const int warp = tid >> 5;
    const int wm   = warp & 3;   // 4 warps along M
    const int wn   = warp >> 2;  // 2 warps along N
    const int bm   = blockIdx.y;
    const int bn   = blockIdx.x;

    const float* Ag = A + (size_t)bm * BM * DIN;
    const float* Bg = B + (size_t)bn * BN * DIN;

    // global->smem copy mapping: each thread copies 4x 16B per tile
    const int lr = tid >> 2;          // 0..63
    const int lc = (tid & 3) * 4;     // word column within BK=16

    float acc[2][8][4];
    #pragma unroll
    for (int i = 0; i < 2; i++)
        #pragma unroll
        for (int j = 0; j < 8; j++)
            #pragma unroll
            for (int k = 0; k < 4; k++)
                acc[i][j][k] = 0.f;

    const int NT = DIN / BK;  // 256

    // ---- prologue: fill STAGES-1 buffers ----
    #pragma unroll
    for (int s = 0; s < STAGES - 1; ++s) {
        float* sA = sm + s * STAGE_W;
        float* sB = sA + TILE_W;
        const float* ga = Ag + s * BK;
        const float* gb = Bg + s * BK;
        cp_async16(sA + lr * PITCH + lc,          ga + (size_t)lr * DIN + lc);
        cp_async16(sA + (lr + 64) * PITCH + lc,   ga + (size_t)(lr + 64) * DIN + lc);
        cp_async16(sB + lr * PITCH + lc,          gb + (size_t)lr * DIN + lc);
        cp_async16(sB + (lr + 64) * PITCH + lc,   gb + (size_t)(lr + 64) * DIN + lc);
        cp_commit();
    }

    const int a_off = (wm * 32 + (lane >> 2)) * PITCH + (lane & 3);
    const int b_off = (wn * 64 + (lane >> 2)) * PITCH + (lane & 3);

    // ---- mainloop ----
    for (int c = 0; c < NT; ++c) {
        cp_wait<STAGES - 2>();
        __syncthreads();

        const int f = c + STAGES - 1;
        if (f < NT) {
            float* sA = sm + (f % STAGES) * STAGE_W;
            float* sB = sA + TILE_W;
            const float* ga = Ag + f * BK;
            const float* gb = Bg + f * BK;
            cp_async16(sA + lr * PITCH + lc,          ga + (size_t)lr * DIN + lc);
            cp_async16(sA + (lr + 64) * PITCH + lc,   ga + (size_t)(lr + 64) * DIN + lc);
            cp_async16(sB + lr * PITCH + lc,          gb + (size_t)lr * DIN + lc);
            cp_async16(sB + (lr + 64) * PITCH + lc,   gb + (size_t)(lr + 64) * DIN + lc);
        }
        cp_commit();  // commit every iter (possibly empty) to keep group counting uniform

        const float* sA = sm + (c % STAGES) * STAGE_W;
        const float* sB = sA + TILE_W;
        const float* aw = sA + a_off;
        const float* bw = sB + b_off;

        #pragma unroll
        for (int kk = 0; kk < BK; kk += 8) {
            uint32_t af[2][4];
            #pragma unroll
            for (int i = 0; i < 2; i++) {
                const float* p = aw + i * (16 * PITCH) + kk;
                af[i][0] = f2tf(p[0]);
                af[i][1] = f2tf(p[8 * PITCH]);
                af[i][2] = f2tf(p[4]);
                af[i][3] = f2tf(p[8 * PITCH + 4]);
            }
            uint32_t bfr[8][2];
            #pragma unroll
            for (int j = 0; j < 8; j++) {
                const float* p = bw + j * (8 * PITCH) + kk;
                bfr[j][0] = f2tf(p[0]);
                bfr[j][1] = f2tf(p[4]);
            }
            #pragma unroll
            for (int i = 0; i < 2; i++)
                #pragma unroll
                for (int j = 0; j < 8; j++)
                    mma_tf32(acc[i][j][0], acc[i][j][1], acc[i][j][2], acc[i][j][3],
                             af[i][0], af[i][1], af[i][2], af[i][3],
                             bfr[j][0], bfr[j][1]);
        }
    }

    // ---- epilogue ----
    #pragma unroll
    for (int i = 0; i < 2; i++) {
        #pragma unroll
        for (int h = 0; h < 2; h++) {
            const int m = bm * BM + wm * 32 + i * 16 + (lane >> 2) + h * 8;

            if (MODE == 0) {
                // u-pass: write scaled u_all rows (pitch 128, bn == 0)
                #pragma unroll
                for (int j = 0; j < 8; j++) {
                    const int n = wn * 64 + j * 8 + (lane & 3) * 2;
                    const float s = scal[n >> 4];
                    float2 v;
                    v.x = acc[i][j][h * 2 + 0] * s;
                    v.y = acc[i][j][h * 2 + 1] * s;
                    *reinterpret_cast<float2*>(&g_u[(size_t)m * 128 + n]) = v;
                }
            } else {
                const int slot = t2s[m];
                float4 u[4];
                const float* Bbase = nullptr;
                if (slot >= 0) {
                    const float4* up = reinterpret_cast<const float4*>(
                        &g_u[(size_t)m * 128 + slot * RANK]);
                    u[0] = up[0]; u[1] = up[1]; u[2] = up[2]; u[3] = up[3];
                    Bbase = loraB + (size_t)slot * DOUT * RANK;
                }
                float* crow = C + (size_t)m * DOUT;
                #pragma unroll
                for (int j = 0; j < 8; j++) {
                    const int n = bn * BN + wn * 64 + j * 8 + (lane & 3) * 2;
                    float d0 = 0.f, d1 = 0.f;
                    if (slot >= 0) {
                        d0 = dot16(u, Bbase + (size_t)n * RANK);
                        d1 = dot16(u, Bbase + (size_t)(n + 1) * RANK);
                    }
                    float2 v;
                    v.x = acc[i][j][h * 2 + 0] + bias[n]     + d0;
                    v.y = acc[i][j][h * 2 + 1] + bias[n + 1] + d1;
                    *reinterpret_cast<float2*>(&crow[n]) = v;
                }
            }
        }
    }
}

extern "C" void kernel_launch(void* const* d_in, const int* in_sizes, int n_in,
                              void* d_out, int out_size)
{
    const float* x     = (const float*)d_in[0];
    const int*   t2s   = (const int*)  d_in[1];   // token_to_slot (values 0..7)
    const float* w     = (const float*)d_in[2];   // [DOUT][DIN]
    const float* bias  = (const float*)d_in[3];
    const float* lA    = (const float*)d_in[4];   // [S][R][DIN] == [128][DIN]
    const float* lB    = (const float*)d_in[5];   // [S][DOUT][R]
    const float* scal  = (const float*)d_in[6];
    float*       y     = (float*)d_out;

    cudaFuncSetAttribute(gemm_tf32<0>, cudaFuncAttributeMaxDynamicSharedMemorySize, SMEM_BYTES);
    cudaFuncSetAttribute(gemm_tf32<1>, cudaFuncAttributeMaxDynamicSharedMemorySize, SMEM_BYTES);

    // Pass A: u_all = (x @ lora_A_flat^T) * scaling  -> g_u [TOK x 128]
    gemm_tf32<0><<<dim3(1, TOK / BM), 256, SMEM_BYTES>>>(
        x, lA, nullptr, nullptr, nullptr, nullptr, scal);

    // Pass B: y = x @ W^T + bias + LoRA-B epilogue
    gemm_tf32<1><<<dim3(DOUT / BN, TOK / BM), 256, SMEM_BYTES>>>(
        x, w, y, bias, t2s, lB, nullptr);
}

// round 3
// speedup vs baseline: 1.9433x; 1.9433x over previous
#include <cuda_runtime.h>
#include <cstdint>

// ---------------------------------------------------------------------------
// LoRARowParallelLinear, mma.sync tf32 path (compute_103-safe; no tcgen05).
//   conv:   RNA-round + repack x, W, lora_A into FRAGMENT-MAJOR layouts;
//           build Bcat[n][s*16+r] (fragment-major).
//   pass A: u[T,128] = mask*scal*(x @ lora_A^T), written in A-frag layout.
//   pass B: y = x @ W^T (K=4096) + u @ Bcat^T (K-ext 128, same accum) + bias.
// Fragment-major: A tile (16m x 8k) = 128 floats, thread l's LDS.128 at
// l*16B yields (a0,a1,a2,a3). B tile (8n x 8k) = 64 floats, LDS.64 -> (b0,b1).
// ---------------------------------------------------------------------------

#define DEVINL static __device__ __forceinline__

namespace {
constexpr int TOK = 8192, DIN = 4096, DOUT = 4096;
constexpr int KB_MAIN = DIN / 8;   // 512 k-blocks of 8
constexpr int KB_EXT  = 16;        // 128/8
}

// scratch (allocation-free: __device__ globals), all fragment-major
__device__ float g_xc  [TOK  * DIN];   // A-blocks: [TOK/16][512][128]
__device__ float g_wc  [DOUT * DIN];   // B-blocks: [DOUT/8][512][64]
__device__ float g_lac [128  * DIN];   // B-blocks: [16][512][64]
__device__ float g_bcat[DOUT * 128];   // B-blocks: [DOUT/8][16][64]
__device__ float g_u   [TOK  * 128];   // A-blocks: [TOK/16][16][128]

DEVINL uint32_t f2tf(float f) { uint32_t u; asm("cvt.rna.tf32.f32 %0, %1;" : "=r"(u) : "f"(f)); return u; }
DEVINL float    rna(float f)  { return __uint_as_float(f2tf(f)); }

DEVINL void mma_tf32(float& d0, float& d1, float& d2, float& d3,
                     uint32_t a0, uint32_t a1, uint32_t a2, uint32_t a3,
                     uint32_t b0, uint32_t b1)
{
    asm volatile(
        "mma.sync.aligned.m16n8k8.row.col.f32.tf32.tf32.f32 "
        "{%0,%1,%2,%3},{%4,%5,%6,%7},{%8,%9},{%0,%1,%2,%3};"
        : "+f"(d0), "+f"(d1), "+f"(d2), "+f"(d3)
        : "r"(a0), "r"(a1), "r"(a2), "r"(a3), "r"(b0), "r"(b1));
}

DEVINL void cpa16(float* smem_dst, const float* gsrc) {
    uint32_t s = (uint32_t)__cvta_generic_to_shared(smem_dst);
    asm volatile("cp.async.cg.shared.global [%0], [%1], 16;" :: "r"(s), "l"(gsrc));
}
DEVINL void cpcommit() { asm volatile("cp.async.commit_group;"); }
template <int N> DEVINL void cpwait() { asm volatile("cp.async.wait_group %0;" :: "n"(N)); }

// ---------------------------------------------------------------------------
// Conversion: RNA-round + repack into fragment-major layouts.
// ---------------------------------------------------------------------------
__global__ void conv_kernel(const float* __restrict__ x, const float* __restrict__ w,
                            const float* __restrict__ la, const float* __restrict__ lb)
{
    const int tid   = blockIdx.x * blockDim.x + threadIdx.x;
    const int lane  = tid & 31;
    const int gwarp = tid >> 5;
    const int nwarp = (gridDim.x * blockDim.x) >> 5;

    const int r0 = lane >> 2, c0 = lane & 3;

    // x -> g_xc  (A-frag blocks, 512x512 blocks)
    for (int blk = gwarp; blk < (TOK / 16) * KB_MAIN; blk += nwarp) {
        const int mt = blk >> 9, kt = blk & 511;
        const float* base = x + (size_t)(mt * 16) * DIN + kt * 8;
        float4 v;
        v.x = rna(base[(size_t)r0 * DIN + c0]);
        v.y = rna(base[(size_t)(r0 + 8) * DIN + c0]);
        v.z = rna(base[(size_t)r0 * DIN + c0 + 4]);
        v.w = rna(base[(size_t)(r0 + 8) * DIN + c0 + 4]);
        *reinterpret_cast<float4*>(g_xc + (size_t)blk * 128 + lane * 4) = v;
    }
    // w -> g_wc  (B-frag blocks, 512x512 blocks)
    for (int blk = gwarp; blk < (DOUT / 8) * KB_MAIN; blk += nwarp) {
        const int nt = blk >> 9, kt = blk & 511;
        const float* base = w + (size_t)(nt * 8) * DIN + kt * 8;
        float2 v;
        v.x = rna(base[(size_t)r0 * DIN + c0]);
        v.y = rna(base[(size_t)r0 * DIN + c0 + 4]);
        *reinterpret_cast<float2*>(g_wc + (size_t)blk * 64 + lane * 2) = v;
    }
    // lora_A (flat [128][DIN]) -> g_lac  (B-frag blocks, 16x512)
    for (int blk = gwarp; blk < 16 * KB_MAIN; blk += nwarp) {
        const int nt = blk >> 9, kt = blk & 511;
        const float* base = la + (size_t)(nt * 8) * DIN + kt * 8;
        float2 v;
        v.x = rna(base[(size_t)r0 * DIN + c0]);
        v.y = rna(base[(size_t)r0 * DIN + c0 + 4]);
        *reinterpret_cast<float2*>(g_lac + (size_t)blk * 64 + lane * 2) = v;
    }
    // lora_B [8][DOUT][16] -> g_bcat (B-frag blocks [DOUT/8][16][64]):
    //   Bcat[n][s*16+r] = lB[s][n][r]
    const int nth = gridDim.x * blockDim.x;
    for (int i = tid; i < 8 * DOUT * 16; i += nth) {
        const int s = i >> 16;
        const int n = (i >> 4) & 4095;
        const int r = i & 15;
        const float val = rna(lb[i]);
        const int kc  = s * 16 + r;
        const int nt  = n >> 3, kb = kc >> 3, col = kc & 7;
        const int off = ((n & 7) * 4 + (col & 3)) * 2 + (col >> 2);
        g_bcat[((size_t)nt * 16 + kb) * 64 + off] = val;
    }
}

// ---------------------------------------------------------------------------
// GEMM: CTA tile BM x BN, warp tile 32x64, BK=32 per stage, 3 stages.
//  MODE 0: 128x128, 8 warps; A=g_xc, B=g_lac; epi: mask*scal -> g_u (A-frag)
//  MODE 1: 128x256, 16 warps; A=g_xc, B=g_wc; f>=128 reads g_u/g_bcat (K-ext);
//          epi: + bias -> y
// ---------------------------------------------------------------------------
template <int MODE>
struct Cfg;
template <> struct Cfg<0> { static constexpr int BM=128, BN=128, WN=2, TH=256, NT=128, KEXT=0; };
template <> struct Cfg<1> { static constexpr int BM=128, BN=256, WN=4, TH=512, NT=132, KEXT=1; };

template <int MODE>
__global__ void __launch_bounds__(Cfg<MODE>::TH, 1) gemm_frag(
    float* __restrict__ C, const float* __restrict__ bias,
    const int* __restrict__ t2s, const float* __restrict__ scal)
{
    constexpr int BM = Cfg<MODE>::BM, BN = Cfg<MODE>::BN;
    constexpr int WN = Cfg<MODE>::WN, TH = Cfg<MODE>::TH, NT = Cfg<MODE>::NT;
    constexpr int A_ST = BM * 32;          // stage A floats (BM*128 bytes)
    constexpr int B_ST = BN * 32;
    constexpr int STW  = A_ST + B_ST;

    extern __shared__ float sm[];
    const int tid  = threadIdx.x;
    const int lane = tid & 31;
    const int warp = tid >> 5;
    const int wn   = warp % WN;
    const int wm   = warp / WN;
    const int bm   = blockIdx.y, bn = blockIdx.x;

    float acc[2][8][4];
    #pragma unroll
    for (int i = 0; i < 2; i++)
        #pragma unroll
        for (int j = 0; j < 8; j++)
            #pragma unroll
            for (int k = 0; k < 4; k++) acc[i][j][k] = 0.f;

    auto load_stage = [&](int f, int buf) {
        float* sA = sm + buf * STW;
        float* sB = sA + A_ST;
        // A: BM*8 16B-chunks
        #pragma unroll
        for (int q = tid; q < BM * 8; q += TH) {
            const int mt = q >> 7, rem = q & 127, kt = rem >> 5, c = rem & 31;
            const float* src;
            if (!Cfg<MODE>::KEXT || f < 128)
                src = g_xc + ((size_t)(bm * (BM / 16) + mt) * KB_MAIN + f * 4 + kt) * 128 + c * 4;
            else
                src = g_u  + ((size_t)(bm * (BM / 16) + mt) * KB_EXT + (f - 128) * 4 + kt) * 128 + c * 4;
            cpa16(sA + (mt * 4 + kt) * 128 + c * 4, src);
        }
        // B: BN*8 16B-chunks
        #pragma unroll
        for (int q = tid; q < BN * 8; q += TH) {
            const int nt = q >> 6, kt = (q >> 4) & 3, c = q & 15;
            const float* src;
            if (MODE == 0)
                src = g_lac + ((size_t)nt * KB_MAIN + f * 4 + kt) * 64 + c * 4;
            else if (f < 128)
                src = g_wc  + ((size_t)(bn * (BN / 8) + nt) * KB_MAIN + f * 4 + kt) * 64 + c * 4;
            else
                src = g_bcat + ((size_t)(bn * (BN / 8) + nt) * KB_EXT + (f - 128) * 4 + kt) * 64 + c * 4;
            cpa16(sB + (nt * 4 + kt) * 64 + c * 4, src);
        }
    };

    load_stage(0, 0); cpcommit();
    load_stage(1, 1); cpcommit();

    for (int ci = 0; ci < NT; ci++) {
        cpwait<1>();
        __syncthreads();

        if (ci + 2 < NT) load_stage(ci + 2, (ci + 2) % 3);
        cpcommit();

        const float* sA = sm + (ci % 3) * STW;
        const float* sB = sA + A_ST;
        const uint32_t* aw = reinterpret_cast<const uint32_t*>(sA) + (wm * 2) * 4 * 128 + lane * 4;
        const uint32_t* bw = reinterpret_cast<const uint32_t*>(sB) + (wn * 8) * 4 * 64 + lane * 2;

        #pragma unroll
        for (int kt = 0; kt < 4; kt++) {
            uint4 a[2];
            a[0] = *reinterpret_cast<const uint4*>(aw + kt * 128);
            a[1] = *reinterpret_cast<const uint4*>(aw + (4 + kt) * 128);
            uint2 b[8];
            #pragma unroll
            for (int j = 0; j < 8; j++)
                b[j] = *reinterpret_cast<const uint2*>(bw + (j * 4 + kt) * 64);
            #pragma unroll
            for (int i = 0; i < 2; i++)
                #pragma unroll
                for (int j = 0; j < 8; j++)
                    mma_tf32(acc[i][j][0], acc[i][j][1], acc[i][j][2], acc[i][j][3],
                             a[i].x, a[i].y, a[i].z, a[i].w, b[j].x, b[j].y);
        }
    }

    // ---- epilogue ----
    if (MODE == 1) {
        const int nb = bn * BN + wn * 64;
        #pragma unroll
        for (int i = 0; i < 2; i++) {
            #pragma unroll
            for (int h = 0; h < 2; h++) {
                const int m = bm * BM + wm * 32 + i * 16 + h * 8 + (lane >> 2);
                float* crow = C + (size_t)m * DOUT + nb + (lane & 3) * 2;
                #pragma unroll
                for (int j = 0; j < 8; j++) {
                    const float2 bv = *reinterpret_cast<const float2*>(
                        bias + nb + j * 8 + (lane & 3) * 2);
                    float2 v;
                    v.x = acc[i][j][h * 2 + 0] + bv.x;
                    v.y = acc[i][j][h * 2 + 1] + bv.y;
                    *reinterpret_cast<float2*>(crow + j * 8) = v;
                }
            }
        }
    } else {
        #pragma unroll
        for (int i = 0; i < 2; i++) {
            #pragma unroll
            for (int h = 0; h < 2; h++) {
                const int m    = bm * BM + wm * 32 + i * 16 + h * 8 + (lane >> 2);
                const int slot = t2s[m];
                const float sc = (slot >= 0) ? scal[slot] : 0.f;
                const int mt = m >> 4, row = m & 15;
                const int rowoff = (row & 7) * 4, regbit = row >> 3;
                float* ublk = g_u + (size_t)mt * 16 * 128;
                #pragma unroll
                for (int j = 0; j < 8; j++) {
                    #pragma unroll
                    for (int r = 0; r < 2; r++) {
                        const int nn  = wn * 64 + j * 8 + (lane & 3) * 2 + r;
                        const int kb  = nn >> 3, col = nn & 7;
                        const int off = (rowoff + (col & 3)) * 4 + regbit + 2 * (col >> 2);
                        const float val = ((nn >> 4) == slot)
                                          ? rna(acc[i][j][h * 2 + r] * sc) : 0.f;
                        ublk[kb * 128 + off] = val;
                    }
                }
            }
        }
    }
}

// ---------------------------------------------------------------------------
extern "C" void kernel_launch(void* const* d_in, const int* in_sizes, int n_in,
                              void* d_out, int out_size)
{
    const float* x    = (const float*)d_in[0];
    const int*   t2s  = (const int*)  d_in[1];
    const float* w    = (const float*)d_in[2];
    const float* bias = (const float*)d_in[3];
    const float* lA   = (const float*)d_in[4];
    const float* lB   = (const float*)d_in[5];
    const float* scal = (const float*)d_in[6];
    float*       y    = (float*)d_out;

    constexpr int SMEM0 = 3 * (128 + 128) * 128;  //  96 KB
    constexpr int SMEM1 = 3 * (128 + 256) * 128;  // 144 KB

    cudaFuncSetAttribute(gemm_frag<0>, cudaFuncAttributeMaxDynamicSharedMemorySize, SMEM0);
    cudaFuncSetAttribute(gemm_frag<1>, cudaFuncAttributeMaxDynamicSharedMemorySize, SMEM1);

    // 1) convert + repack (RNA tf32 rounding, fragment-major)
    conv_kernel<<<592, 256>>>(x, w, lA, lB);

    // 2) pass A: u = mask*scal*(x @ lora_A^T) -> g_u (A-frag layout)
    gemm_frag<0><<<dim3(1, TOK / 128), Cfg<0>::TH, SMEM0>>>(nullptr, nullptr, t2s, scal);

    // 3) pass B: y = x @ W^T (+ LoRA K-ext) + bias
    gemm_frag<1><<<dim3(DOUT / 256, TOK / 128), Cfg<1>::TH, SMEM1>>>(y, bias, t2s, scal);
}